// round 10
// baseline (speedup 1.0000x reference)
#include <cuda_runtime.h>
#include <cuda_fp16.h>
#include <cstdint>

// ---------------- problem constants ----------------
#define N_ROWS   16384
#define N_CODES  8192
#define DIM      512
#define Q_ELEMS  (N_ROWS * DIM)

// ---------------- GEMM tiling (int8, m16n8k32) ----------------
#define BM 128
#define BN 128
#define KCB 128               // K elems (bytes) per stage per row
#define NSTAGES (DIM / KCB)   // 4
#define CH 8                  // codes per argmin chunk
#define NCH (N_CODES / CH)    // 1024 chunk-mins per row
#define EPS 4.0e-4f
#define MAXCAND 64            // max candidate chunks per row

#define SX 22.0f
#define SE (127.0f * 8192.0f)
#define DSCALE (2.0f / (SX * SE))

// dynamic smem: 3 stages x (A 16KB + B 16KB) = 98304; enorm after
#define STG_BYTES 32768
#define SM_BOFF   16384
#define SM_ENORM  98304
#define SM_TOTAL  (98304 + 512)

// ---------------- scratch (device globals; no allocation allowed) ----------------
__device__ __align__(256) int8_t g_qx[(size_t)N_ROWS * DIM];
__device__ __align__(256) int8_t g_qe[(size_t)N_CODES * DIM];
__device__ float  g_xnorm[N_ROWS];
__device__ float  g_enorm[N_CODES];
__device__ __align__(16) __half g_cmin[(size_t)N_ROWS * NCH];
__device__ float  g_rowsq[N_ROWS];
__device__ int    g_cand[(size_t)N_ROWS * MAXCAND];
__device__ int    g_ccount[N_ROWS];
__device__ int    g_maxidx;

// ---------------- PTX helpers ----------------
__device__ __forceinline__ uint32_t smem_u32(const void* p) {
    uint32_t a;
    asm("{ .reg .u64 t; cvta.to.shared.u64 t, %1; cvt.u32.u64 %0, t; }"
        : "=r"(a) : "l"(p));
    return a;
}
__device__ __forceinline__ void cp16(uint32_t dst, const void* src) {
    asm volatile("cp.async.cg.shared.global [%0], [%1], 16;" :: "r"(dst), "l"(src) : "memory");
}
#define CP_COMMIT() asm volatile("cp.async.commit_group;" ::: "memory")
#define CP_WAIT(n)  asm volatile("cp.async.wait_group %0;" :: "n"(n) : "memory")

#define SWZ(b) ((b) ^ (((b) >> 3) & 0x70))

__device__ __forceinline__ void ldsm4(uint32_t* r, uint32_t addr) {
    asm volatile("ldmatrix.sync.aligned.m8n8.x4.shared.b16 {%0,%1,%2,%3}, [%4];"
                 : "=r"(r[0]), "=r"(r[1]), "=r"(r[2]), "=r"(r[3]) : "r"(addr));
}
__device__ __forceinline__ void mma_s8(int* c, const uint32_t* a, const uint32_t* b) {
    asm volatile(
        "mma.sync.aligned.m16n8k32.row.col.s32.s8.s8.s32 "
        "{%0,%1,%2,%3}, {%4,%5,%6,%7}, {%8,%9}, {%0,%1,%2,%3};"
        : "+r"(c[0]), "+r"(c[1]), "+r"(c[2]), "+r"(c[3])
        : "r"(a[0]), "r"(a[1]), "r"(a[2]), "r"(a[3]), "r"(b[0]), "r"(b[1]));
}
__device__ __forceinline__ int q8(float f) {
    int v = __float2int_rn(f);
    return max(-127, min(127, v));
}

// ---------------- kernels ----------------
__global__ void init_kernel() { g_maxidx = 0; }

// one warp per row: fp32 norm + int8 quantize
__global__ void convert_kernel(const float* __restrict__ x, const float* __restrict__ emb) {
    int warp = (blockIdx.x * blockDim.x + threadIdx.x) >> 5;
    int lane = threadIdx.x & 31;
    const float* src; int8_t* dst; float* nrm; int row; float sc;
    if (warp < N_ROWS) { src = x; dst = g_qx; nrm = g_xnorm; row = warp; sc = SX; }
    else               { src = emb; dst = g_qe; nrm = g_enorm; row = warp - N_ROWS; sc = SE; }
    const float4* p = reinterpret_cast<const float4*>(src + (size_t)row * DIM);
    uint32_t* o = reinterpret_cast<uint32_t*>(dst + (size_t)row * DIM);
    float s = 0.f;
    #pragma unroll
    for (int c = lane; c < DIM / 4; c += 32) {
        float4 v = p[c];
        s += v.x * v.x + v.y * v.y + v.z * v.z + v.w * v.w;
        int q0 = q8(v.x * sc), q1 = q8(v.y * sc), q2 = q8(v.z * sc), q3 = q8(v.w * sc);
        o[c] = (uint32_t)(q0 & 0xff) | ((uint32_t)(q1 & 0xff) << 8)
             | ((uint32_t)(q2 & 0xff) << 16) | ((uint32_t)(q3 & 0xff) << 24);
    }
    #pragma unroll
    for (int off = 16; off; off >>= 1) s += __shfl_xor_sync(0xffffffffu, s, off);
    if (lane == 0) nrm[row] = s;
}

// int8 IMMA GEMM: 128x128xK512 per CTA, 256 thr, 3-buffer cp.async, ONE sync/stage.
// Epilogue: d~ = enorm - DSCALE*dot, per-row min over 8-code chunks -> g_cmin (fp16).
__global__ void __launch_bounds__(256, 2) vq_gemm_kernel() {
    extern __shared__ __align__(1024) char smem[];
    const int tid = threadIdx.x;
    const int w = tid >> 5, l = tid & 31;
    const int rowBase = blockIdx.x * BM;
    const int cb = blockIdx.y * BN;
    const uint32_t sb = smem_u32(smem);
    float* senorm = reinterpret_cast<float*>(smem + SM_ENORM);

    if (tid < BN) senorm[tid] = g_enorm[cb + tid];

    // warp layout: 2 (M) x 4 (N); warp tile 64 x 32
    const int m0 = (w >> 2) * 64;
    const int n0 = (w & 3) * 32;
    const int aRowLane = l & 15;
    const int aChunkHi = l >> 4;
    const int bRowLane = ((l >> 4) & 1) * 8 + (l & 7);
    const int bChunkHi = (l >> 3) & 1;

    int c[4][4][4];
    #pragma unroll
    for (int mt = 0; mt < 4; mt++)
        #pragma unroll
        for (int nt = 0; nt < 4; nt++)
            #pragma unroll
            for (int e = 0; e < 4; e++) c[mt][nt][e] = 0;

    auto load_stage = [&](int kc, int s) {
        const int kb = kc * KCB;
        const uint32_t stg = sb + (uint32_t)s * STG_BYTES;
        #pragma unroll
        for (int q = 0; q < 4; q++) {            // A: 128 rows x 8 x 16B
            int t = tid + q * 256;
            int r = t >> 3, ch = t & 7;
            cp16(stg + SWZ((uint32_t)(r * 128 + ch * 16)),
                 g_qx + (size_t)(rowBase + r) * DIM + kb + ch * 16);
        }
        #pragma unroll
        for (int q = 0; q < 4; q++) {            // B: 128 rows x 8 x 16B
            int t = tid + q * 256;
            int r = t >> 3, ch = t & 7;
            cp16(stg + SM_BOFF + SWZ((uint32_t)(r * 128 + ch * 16)),
                 g_qe + (size_t)(cb + r) * DIM + kb + ch * 16);
        }
        CP_COMMIT();
    };

    load_stage(0, 0);
    load_stage(1, 1);

    #pragma unroll
    for (int i = 0; i < NSTAGES; i++) {
        if (i < NSTAGES - 1) CP_WAIT(1); else CP_WAIT(0);
        __syncthreads();
        if (i + 2 < NSTAGES) load_stage(i + 2, (i + 2) % 3);
        const uint32_t aStg = sb + (uint32_t)(i % 3) * STG_BYTES;
        const uint32_t bStg = aStg + SM_BOFF;
        #pragma unroll
        for (int ks = 0; ks < 4; ks++) {          // 4 x K32 per 128B stage
            uint32_t a[4][4], b[4][2];
            #pragma unroll
            for (int mt = 0; mt < 4; mt++) {
                uint32_t off = (uint32_t)((m0 + mt * 16 + aRowLane) * 128
                                          + (ks * 2 + aChunkHi) * 16);
                ldsm4(a[mt], aStg + SWZ(off));
            }
            #pragma unroll
            for (int nt2 = 0; nt2 < 2; nt2++) {
                uint32_t r4[4];
                uint32_t off = (uint32_t)((n0 + nt2 * 16 + bRowLane) * 128
                                          + (ks * 2 + bChunkHi) * 16);
                ldsm4(r4, bStg + SWZ(off));
                b[nt2 * 2][0] = r4[0]; b[nt2 * 2][1] = r4[1];
                b[nt2 * 2 + 1][0] = r4[2]; b[nt2 * 2 + 1][1] = r4[3];
            }
            #pragma unroll
            for (int mt = 0; mt < 4; mt++)
                #pragma unroll
                for (int nt = 0; nt < 4; nt++)
                    mma_s8(c[mt][nt], a[mt], b[nt]);
        }
    }

    // ---- epilogue: chunk (8-code) mins -> smem staging -> coalesced fp16 gmem
    __syncthreads();
    float* sbuf = reinterpret_cast<float*>(smem);   // [128][20]

    #pragma unroll
    for (int mt = 0; mt < 4; mt++) {
        #pragma unroll
        for (int nt = 0; nt < 4; nt++) {
            const int colBase = n0 + nt * 8 + (l & 3) * 2;
            float en0 = senorm[colBase], en1 = senorm[colBase + 1];
            float v0 = fminf(en0 - DSCALE * (float)c[mt][nt][0],
                             en1 - DSCALE * (float)c[mt][nt][1]);
            float v1 = fminf(en0 - DSCALE * (float)c[mt][nt][2],
                             en1 - DSCALE * (float)c[mt][nt][3]);
            #pragma unroll
            for (int off = 1; off <= 2; off <<= 1) {
                v0 = fminf(v0, __shfl_xor_sync(0xffffffffu, v0, off));
                v1 = fminf(v1, __shfl_xor_sync(0xffffffffu, v1, off));
            }
            if ((l & 3) == 0) {
                int rloc = m0 + mt * 16 + (l >> 2);
                int chLoc = (w & 3) * 4 + nt;
                sbuf[rloc * 20 + chLoc] = v0;
                sbuf[(rloc + 8) * 20 + chLoc] = v1;
            }
        }
    }
    __syncthreads();
    {
        int row = tid >> 1, half = tid & 1;
        const float* s = &sbuf[row * 20 + half * 8];
        __half2 p0 = __floats2half2_rn(s[0], s[1]);
        __half2 p1 = __floats2half2_rn(s[2], s[3]);
        __half2 p2 = __floats2half2_rn(s[4], s[5]);
        __half2 p3 = __floats2half2_rn(s[6], s[7]);
        uint4 o;
        o.x = *reinterpret_cast<unsigned*>(&p0);
        o.y = *reinterpret_cast<unsigned*>(&p1);
        o.z = *reinterpret_cast<unsigned*>(&p2);
        o.w = *reinterpret_cast<unsigned*>(&p3);
        __half* dst = &g_cmin[(size_t)(blockIdx.x * BM + row) * NCH + blockIdx.y * 16 + half * 8];
        *reinterpret_cast<uint4*>(dst) = o;
    }
}

// warp-per-row streaming scan over fp16 g_cmin: min -> threshold -> compact
// candidate chunk ids. grid N_ROWS/8, block 256. No smem, no block syncs.
__global__ void __launch_bounds__(256) scan_kernel() {
    const int lane = threadIdx.x & 31;
    const int row = blockIdx.x * 8 + (threadIdx.x >> 5);

    const uint4* cm = reinterpret_cast<const uint4*>(&g_cmin[(size_t)row * NCH]);
    float2 f[4][4];
    float lmin = 3.4028235e38f;
    #pragma unroll
    for (int q = 0; q < 4; q++) {
        uint4 u = cm[lane + 32 * q];
        f[q][0] = __half22float2(*reinterpret_cast<__half2*>(&u.x));
        f[q][1] = __half22float2(*reinterpret_cast<__half2*>(&u.y));
        f[q][2] = __half22float2(*reinterpret_cast<__half2*>(&u.z));
        f[q][3] = __half22float2(*reinterpret_cast<__half2*>(&u.w));
        #pragma unroll
        for (int pj = 0; pj < 4; pj++)
            lmin = fminf(lmin, fminf(f[q][pj].x, f[q][pj].y));
    }
    #pragma unroll
    for (int off = 16; off; off >>= 1) lmin = fminf(lmin, __shfl_xor_sync(0xffffffffu, lmin, off));
    const float thr = lmin + EPS;

    int cnt = 0;
    int* cand = &g_cand[(size_t)row * MAXCAND];
    #pragma unroll
    for (int q = 0; q < 4; q++) {
        #pragma unroll
        for (int pj = 0; pj < 4; pj++) {
            #pragma unroll
            for (int e = 0; e < 2; e++) {
                float ve = e ? f[q][pj].y : f[q][pj].x;
                unsigned m = __ballot_sync(0xffffffffu, ve <= thr);
                if (m) {
                    if (ve <= thr) {
                        int rank = __popc(m & ((1u << lane) - 1));
                        int p = cnt + rank;
                        if (p < MAXCAND) cand[p] = (lane + 32 * q) * 8 + pj * 2 + e;
                    }
                    cnt += __popc(m);
                }
            }
        }
    }
    if (lane == 0) g_ccount[row] = min(cnt, MAXCAND);
}

// block-per-row exact rescore of candidate codes (flat-parallel across 8 warps,
// packed u64 keys for exact first-index tie-break) + fused gather/ST/rowsq.
__global__ void __launch_bounds__(256) rescore_kernel(const float* __restrict__ x,
                                                      const float* __restrict__ emb,
                                                      float* __restrict__ out) {
    __shared__ __align__(16) float sx[DIM];
    __shared__ float sred[8];
    __shared__ int   slist[MAXCAND];
    __shared__ unsigned long long skey[MAXCAND * CH];
    __shared__ int   sbesti;

    const int row = blockIdx.x;
    const int tid = threadIdx.x, w = tid >> 5, l = tid & 31;

    if (tid < 128)
        reinterpret_cast<float4*>(sx)[tid] =
            reinterpret_cast<const float4*>(x + (size_t)row * DIM)[tid];
    const int count = g_ccount[row];
    if (tid < count) slist[tid] = g_cand[(size_t)row * MAXCAND + tid];
    __syncthreads();

    const int ncodes = count * CH;
    const float xn = g_xnorm[row];

    for (int k = w; k < ncodes; k += 8) {
        const int code = slist[k >> 3] * CH + (k & 7);
        const float4* e4 = reinterpret_cast<const float4*>(emb + (size_t)code * DIM);
        const float4* xs = reinterpret_cast<const float4*>(sx);
        float acc = 0.f;
        #pragma unroll
        for (int t = 0; t < 4; t++) {
            float4 ev = e4[l + 32 * t];
            float4 xv = xs[l + 32 * t];
            acc = fmaf(ev.x, xv.x, acc);
            acc = fmaf(ev.y, xv.y, acc);
            acc = fmaf(ev.z, xv.z, acc);
            acc = fmaf(ev.w, xv.w, acc);
        }
        #pragma unroll
        for (int off = 16; off; off >>= 1) acc += __shfl_xor_sync(0xffffffffu, acc, off);
        if (l == 0) {
            float d = __fsub_rn(__fadd_rn(xn, g_enorm[code]), 2.0f * acc);
            skey[k] = ((unsigned long long)__float_as_uint(d) << 32) | (unsigned)code;
        }
    }
    __syncthreads();

    if (w == 0) {
        unsigned long long best = 0xffffffffffffffffull;
        for (int k = l; k < ncodes; k += 32) best = min(best, skey[k]);
        #pragma unroll
        for (int off = 16; off; off >>= 1) {
            unsigned long long o = __shfl_xor_sync(0xffffffffu, best, off);
            best = min(best, o);
        }
        if (l == 0) {
            int bi = (int)(best & 0xffffffffu);
            sbesti = bi;
            out[Q_ELEMS + 2 + row] = (float)bi;
            atomicMax(&g_maxidx, bi);
        }
    }
    __syncthreads();
    const int idx = sbesti;

    const float2* q2 = reinterpret_cast<const float2*>(emb + (size_t)idx * DIM);
    const float2* x2 = reinterpret_cast<const float2*>(sx);
    float2 qv = q2[tid], xv = x2[tid];
    float2 ov;
    float d0 = __fsub_rn(qv.x, xv.x); ov.x = __fadd_rn(xv.x, d0);
    float d1 = __fsub_rn(qv.y, xv.y); ov.y = __fadd_rn(xv.y, d1);
    reinterpret_cast<float2*>(out + (size_t)row * DIM)[tid] = ov;
    float ss = d0 * d0 + d1 * d1;
    #pragma unroll
    for (int off = 16; off; off >>= 1) ss += __shfl_xor_sync(0xffffffffu, ss, off);
    if (l == 0) sred[w] = ss;
    __syncthreads();
    if (tid == 0) {
        float t = 0.f;
        #pragma unroll
        for (int ww = 0; ww < 8; ww++) t += sred[ww];
        g_rowsq[row] = t;
    }
}

__global__ void scalars_kernel(float* __restrict__ out) {
    __shared__ float red[1024];
    const int tid = threadIdx.x;
    float s = 0.f;
    for (int r = tid; r < N_ROWS; r += 1024) s += g_rowsq[r];
    red[tid] = s;
    __syncthreads();
    #pragma unroll
    for (int st = 512; st > 0; st >>= 1) {
        if (tid < st) red[tid] += red[tid + st];
        __syncthreads();
    }
    if (tid == 0) {
        float mean = red[0] / (float)Q_ELEMS;
        out[Q_ELEMS] = 1.25f * mean;
        float L = (float)(g_maxidx + 1);
        float avg = 1.0f / L;
        out[Q_ELEMS + 1] = expf(-avg * logf(avg + 1e-10f));
    }
}

extern "C" void kernel_launch(void* const* d_in, const int* in_sizes, int n_in,
                              void* d_out, int out_size) {
    const float* x   = (const float*)d_in[0];
    const float* emb = (const float*)d_in[1];
    float* out = (float*)d_out;

    cudaFuncSetAttribute(vq_gemm_kernel, cudaFuncAttributeMaxDynamicSharedMemorySize, SM_TOTAL);

    init_kernel<<<1, 1>>>();
    convert_kernel<<<(N_ROWS + N_CODES) / 8, 256>>>(x, emb);
    vq_gemm_kernel<<<dim3(N_ROWS / BM, N_CODES / BN), 256, SM_TOTAL>>>();
    scan_kernel<<<N_ROWS / 8, 256>>>();
    rescore_kernel<<<N_ROWS, 256>>>(x, emb, out);
    scalars_kernel<<<1, 1024>>>(out);
}

// round 11
// speedup vs baseline: 2.5462x; 2.5462x over previous
#include <cuda_runtime.h>
#include <cuda_fp16.h>
#include <cstdint>

// ---------------- problem constants ----------------
#define N_ROWS   16384
#define N_CODES  8192
#define DIM      512
#define Q_ELEMS  (N_ROWS * DIM)

// ---------------- GEMM tiling (fp16 in, fp16 accum) ----------------
#define BM 128
#define BN 128
#define KC 64                 // K elems per stage = 128 B per row
#define NSTAGES (DIM / KC)    // 8
#define CH 8                  // codes per argmin chunk
#define NCH (N_CODES / CH)    // 1024 chunk-mins per row
#define EPS 4.0e-4f
#define MAXCAND 64            // max candidate chunks per row

// dynamic smem: 3 stages x (A 16KB + B 16KB) = 98304; enorm after
#define STG_BYTES 32768
#define SM_BOFF   16384
#define SM_ENORM  98304
#define SM_TOTAL  (98304 + 512)

// ---------------- scratch (device globals; no allocation allowed) ----------------
__device__ __align__(256) __half g_hx[(size_t)N_ROWS * DIM];
__device__ __align__(256) __half g_he[(size_t)N_CODES * DIM];
__device__ float  g_xnorm[N_ROWS];
__device__ float  g_enorm[N_CODES];
__device__ __align__(16) __half g_cmin[(size_t)N_ROWS * NCH];   // d~ chunk mins, fp16
__device__ float  g_rowsq[N_ROWS];
__device__ int    g_maxidx;

// ---------------- PTX helpers ----------------
__device__ __forceinline__ uint32_t smem_u32(const void* p) {
    uint32_t a;
    asm("{ .reg .u64 t; cvta.to.shared.u64 t, %1; cvt.u32.u64 %0, t; }"
        : "=r"(a) : "l"(p));
    return a;
}
__device__ __forceinline__ void cp16(uint32_t dst, const void* src) {
    asm volatile("cp.async.cg.shared.global [%0], [%1], 16;" :: "r"(dst), "l"(src) : "memory");
}
#define CP_COMMIT() asm volatile("cp.async.commit_group;" ::: "memory")
#define CP_WAIT(n)  asm volatile("cp.async.wait_group %0;" :: "n"(n) : "memory")

#define SWZ(b) ((b) ^ (((b) >> 3) & 0x70))

__device__ __forceinline__ void ldsm4(uint32_t* r, uint32_t addr) {
    asm volatile("ldmatrix.sync.aligned.m8n8.x4.shared.b16 {%0,%1,%2,%3}, [%4];"
                 : "=r"(r[0]), "=r"(r[1]), "=r"(r[2]), "=r"(r[3]) : "r"(addr));
}
// fp16 in, fp16 accum: C/D are 2 b32 regs (4 halves)
__device__ __forceinline__ void mma16816_h(uint32_t* c, const uint32_t* a, const uint32_t* b) {
    asm volatile(
        "mma.sync.aligned.m16n8k16.row.col.f16.f16.f16.f16 "
        "{%0,%1}, {%2,%3,%4,%5}, {%6,%7}, {%0,%1};"
        : "+r"(c[0]), "+r"(c[1])
        : "r"(a[0]), "r"(a[1]), "r"(a[2]), "r"(a[3]), "r"(b[0]), "r"(b[1]));
}

// ---------------- kernels ----------------

// one warp per row: fp32 norm + fp16 convert (block 0 also resets g_maxidx)
__global__ void convert_kernel(const float* __restrict__ x, const float* __restrict__ emb) {
    if (blockIdx.x == 0 && threadIdx.x == 0) g_maxidx = 0;
    int warp = (blockIdx.x * blockDim.x + threadIdx.x) >> 5;
    int lane = threadIdx.x & 31;
    const float* src; __half* dst; float* nrm; int row;
    if (warp < N_ROWS) { src = x; dst = g_hx; nrm = g_xnorm; row = warp; }
    else               { src = emb; dst = g_he; nrm = g_enorm; row = warp - N_ROWS; }
    const float4* p = reinterpret_cast<const float4*>(src + (size_t)row * DIM);
    uint2* o = reinterpret_cast<uint2*>(dst + (size_t)row * DIM);
    float s = 0.f;
    #pragma unroll
    for (int c = lane; c < DIM / 4; c += 32) {
        float4 v = p[c];
        s += v.x * v.x + v.y * v.y + v.z * v.z + v.w * v.w;
        __half2 lo = __floats2half2_rn(v.x, v.y);
        __half2 hi = __floats2half2_rn(v.z, v.w);
        uint2 u;
        u.x = *reinterpret_cast<unsigned*>(&lo);
        u.y = *reinterpret_cast<unsigned*>(&hi);
        o[c] = u;
    }
    #pragma unroll
    for (int off = 16; off; off >>= 1) s += __shfl_xor_sync(0xffffffffu, s, off);
    if (lane == 0) nrm[row] = s;
}

// fp16 HMMA GEMM: 128x128xK512 per CTA, 256 thr, 3-stage cp.async, ONE sync/stage.
// Epilogue: d~ = enorm - 2*dot, per-row min over 8-code chunks -> g_cmin (fp16).
__global__ void __launch_bounds__(256, 2) vq_gemm_kernel() {
    extern __shared__ __align__(1024) char smem[];
    const int tid = threadIdx.x;
    const int w = tid >> 5, l = tid & 31;
    const int rowBase = blockIdx.x * BM;
    const int cb = blockIdx.y * BN;
    const uint32_t sb = smem_u32(smem);
    float* senorm = reinterpret_cast<float*>(smem + SM_ENORM);

    if (tid < BN) senorm[tid] = g_enorm[cb + tid];

    // warp layout: 2 (M) x 4 (N); warp tile 64 x 32
    const int m0 = (w >> 2) * 64;
    const int n0 = (w & 3) * 32;
    const int aRowLane = l & 15;
    const int aChunkHi = l >> 4;
    const int bRowLane = ((l >> 4) & 1) * 8 + (l & 7);
    const int bChunkHi = (l >> 3) & 1;

    uint32_t c[4][4][2];
    #pragma unroll
    for (int mt = 0; mt < 4; mt++)
        #pragma unroll
        for (int nt = 0; nt < 4; nt++) { c[mt][nt][0] = 0u; c[mt][nt][1] = 0u; }

    auto load_stage = [&](int kc, int s) {
        const int kb = kc * KC;
        const uint32_t stg = sb + (uint32_t)s * STG_BYTES;
        #pragma unroll
        for (int q = 0; q < 4; q++) {
            int t = tid + q * 256;
            int r = t >> 3, ch = t & 7;
            cp16(stg + SWZ((uint32_t)(r * 128 + ch * 16)),
                 g_hx + (size_t)(rowBase + r) * DIM + kb + ch * 8);
        }
        #pragma unroll
        for (int q = 0; q < 4; q++) {
            int t = tid + q * 256;
            int r = t >> 3, ch = t & 7;
            cp16(stg + SM_BOFF + SWZ((uint32_t)(r * 128 + ch * 16)),
                 g_he + (size_t)(cb + r) * DIM + kb + ch * 8);
        }
        CP_COMMIT();
    };

    load_stage(0, 0);
    load_stage(1, 1);

    #pragma unroll
    for (int i = 0; i < NSTAGES; i++) {
        if (i < NSTAGES - 1) CP_WAIT(1); else CP_WAIT(0);
        __syncthreads();
        if (i + 2 < NSTAGES) load_stage(i + 2, (i + 2) % 3);
        const uint32_t aStg = sb + (uint32_t)(i % 3) * STG_BYTES;
        const uint32_t bStg = aStg + SM_BOFF;
        #pragma unroll
        for (int ks = 0; ks < 4; ks++) {
            uint32_t a[4][4], b[4][2];
            #pragma unroll
            for (int mt = 0; mt < 4; mt++) {
                uint32_t off = (uint32_t)((m0 + mt * 16 + aRowLane) * 128
                                          + (ks * 2 + aChunkHi) * 16);
                ldsm4(a[mt], aStg + SWZ(off));
            }
            #pragma unroll
            for (int nt2 = 0; nt2 < 2; nt2++) {
                uint32_t r4[4];
                uint32_t off = (uint32_t)((n0 + nt2 * 16 + bRowLane) * 128
                                          + (ks * 2 + bChunkHi) * 16);
                ldsm4(r4, bStg + SWZ(off));
                b[nt2 * 2][0] = r4[0]; b[nt2 * 2][1] = r4[1];
                b[nt2 * 2 + 1][0] = r4[2]; b[nt2 * 2 + 1][1] = r4[3];
            }
            #pragma unroll
            for (int mt = 0; mt < 4; mt++)
                #pragma unroll
                for (int nt = 0; nt < 4; nt++)
                    mma16816_h(c[mt][nt], a[mt], b[nt]);
        }
    }

    // ---- epilogue: chunk (8-code) mins -> smem staging -> coalesced fp16 gmem
    __syncthreads();
    float* sbuf = reinterpret_cast<float*>(smem);   // [128][20]

    #pragma unroll
    for (int mt = 0; mt < 4; mt++) {
        #pragma unroll
        for (int nt = 0; nt < 4; nt++) {
            const int colBase = n0 + nt * 8 + (l & 3) * 2;
            float en0 = senorm[colBase], en1 = senorm[colBase + 1];
            __half2 h0 = *reinterpret_cast<__half2*>(&c[mt][nt][0]);  // row r
            __half2 h1 = *reinterpret_cast<__half2*>(&c[mt][nt][1]);  // row r+8
            float v0 = fminf(en0 - 2.0f * __low2float(h0), en1 - 2.0f * __high2float(h0));
            float v1 = fminf(en0 - 2.0f * __low2float(h1), en1 - 2.0f * __high2float(h1));
            #pragma unroll
            for (int off = 1; off <= 2; off <<= 1) {
                v0 = fminf(v0, __shfl_xor_sync(0xffffffffu, v0, off));
                v1 = fminf(v1, __shfl_xor_sync(0xffffffffu, v1, off));
            }
            if ((l & 3) == 0) {
                int rloc = m0 + mt * 16 + (l >> 2);
                int chLoc = (w & 3) * 4 + nt;
                sbuf[rloc * 20 + chLoc] = v0;
                sbuf[(rloc + 8) * 20 + chLoc] = v1;
            }
        }
    }
    __syncthreads();
    {
        int row = tid >> 1, half = tid & 1;
        const float* s = &sbuf[row * 20 + half * 8];
        __half2 p0 = __floats2half2_rn(s[0], s[1]);
        __half2 p1 = __floats2half2_rn(s[2], s[3]);
        __half2 p2 = __floats2half2_rn(s[4], s[5]);
        __half2 p3 = __floats2half2_rn(s[6], s[7]);
        uint4 o;
        o.x = *reinterpret_cast<unsigned*>(&p0);
        o.y = *reinterpret_cast<unsigned*>(&p1);
        o.z = *reinterpret_cast<unsigned*>(&p2);
        o.w = *reinterpret_cast<unsigned*>(&p3);
        __half* dst = &g_cmin[(size_t)(blockIdx.x * BM + row) * NCH + blockIdx.y * 16 + half * 8];
        *reinterpret_cast<uint4*>(dst) = o;
    }
}

// block-per-row fused select: scan cmin row -> threshold -> exact fp32 rescore
// of candidate codes (flat-parallel, packed u64 keys = exact first-index ties)
// -> fused gather + straight-through + rowsq. grid N_ROWS, block 256.
__global__ void __launch_bounds__(256) select_kernel(const float* __restrict__ x,
                                                     const float* __restrict__ emb,
                                                     float* __restrict__ out) {
    __shared__ __align__(16) float sx[DIM];
    __shared__ float sred[8];
    __shared__ int   slist[MAXCAND];
    __shared__ int   scount;
    __shared__ unsigned long long skey[MAXCAND * CH];
    __shared__ int   sbesti;

    const int row = blockIdx.x;
    const int tid = threadIdx.x, w = tid >> 5, l = tid & 31;

    if (tid < 128)
        reinterpret_cast<float4*>(sx)[tid] =
            reinterpret_cast<const float4*>(x + (size_t)row * DIM)[tid];
    if (tid == 0) scount = 0;

    // scan: each thread holds 4 chunk-mins (uint2 = 4 halves), coalesced 2KB row
    uint2 u = reinterpret_cast<const uint2*>(&g_cmin[(size_t)row * NCH])[tid];
    float2 f0 = __half22float2(*reinterpret_cast<__half2*>(&u.x));
    float2 f1 = __half22float2(*reinterpret_cast<__half2*>(&u.y));
    float lmin = fminf(fminf(f0.x, f0.y), fminf(f1.x, f1.y));
    #pragma unroll
    for (int off = 16; off; off >>= 1) lmin = fminf(lmin, __shfl_xor_sync(0xffffffffu, lmin, off));
    if (l == 0) sred[w] = lmin;
    __syncthreads();
    const float thr = fminf(fminf(fminf(sred[0], sred[1]), fminf(sred[2], sred[3])),
                            fminf(fminf(sred[4], sred[5]), fminf(sred[6], sred[7]))) + EPS;

    float fv[4] = {f0.x, f0.y, f1.x, f1.y};
    #pragma unroll
    for (int e = 0; e < 4; e++) {
        if (fv[e] <= thr) {
            int p = atomicAdd(&scount, 1);
            if (p < MAXCAND) slist[p] = tid * 4 + e;   // unordered is fine (key-min)
        }
    }
    __syncthreads();
    const int count = min(scount, MAXCAND);
    const int ncodes = count * CH;
    const float xn = g_xnorm[row];

    // flat-parallel exact fp32 rescore: warp w handles codes w, w+8, ...
    for (int k = w; k < ncodes; k += 8) {
        const int code = slist[k >> 3] * CH + (k & 7);
        const float4* e4 = reinterpret_cast<const float4*>(emb + (size_t)code * DIM);
        const float4* xs = reinterpret_cast<const float4*>(sx);
        float acc = 0.f;
        #pragma unroll
        for (int t = 0; t < 4; t++) {
            float4 ev = e4[l + 32 * t];
            float4 xv = xs[l + 32 * t];
            acc = fmaf(ev.x, xv.x, acc);
            acc = fmaf(ev.y, xv.y, acc);
            acc = fmaf(ev.z, xv.z, acc);
            acc = fmaf(ev.w, xv.w, acc);
        }
        #pragma unroll
        for (int off = 16; off; off >>= 1) acc += __shfl_xor_sync(0xffffffffu, acc, off);
        if (l == 0) {
            float d = __fsub_rn(__fadd_rn(xn, g_enorm[code]), 2.0f * acc);
            // d > 0 (distances ~512): float bits are order-preserving
            skey[k] = ((unsigned long long)__float_as_uint(d) << 32) | (unsigned)code;
        }
    }
    __syncthreads();

    if (w == 0) {
        unsigned long long best = 0xffffffffffffffffull;
        for (int k = l; k < ncodes; k += 32) best = min(best, skey[k]);
        #pragma unroll
        for (int off = 16; off; off >>= 1) {
            unsigned long long o = __shfl_xor_sync(0xffffffffu, best, off);
            best = min(best, o);
        }
        if (l == 0) {
            int bi = (int)(best & 0xffffffffu);
            sbesti = bi;
            out[Q_ELEMS + 2 + row] = (float)bi;
            atomicMax(&g_maxidx, bi);
        }
    }
    __syncthreads();
    const int idx = sbesti;

    // fused gather + straight-through + rowsq (2 floats per thread)
    const float2* q2 = reinterpret_cast<const float2*>(emb + (size_t)idx * DIM);
    const float2* x2 = reinterpret_cast<const float2*>(sx);
    float2 qv = q2[tid], xv = x2[tid];
    float2 ov;
    float d0 = __fsub_rn(qv.x, xv.x); ov.x = __fadd_rn(xv.x, d0);
    float d1 = __fsub_rn(qv.y, xv.y); ov.y = __fadd_rn(xv.y, d1);
    reinterpret_cast<float2*>(out + (size_t)row * DIM)[tid] = ov;
    float ss = d0 * d0 + d1 * d1;
    #pragma unroll
    for (int off = 16; off; off >>= 1) ss += __shfl_xor_sync(0xffffffffu, ss, off);
    if (l == 0) sred[w] = ss;
    __syncthreads();
    if (tid == 0) {
        float t = 0.f;
        #pragma unroll
        for (int ww = 0; ww < 8; ww++) t += sred[ww];
        g_rowsq[row] = t;
    }
}

__global__ void scalars_kernel(float* __restrict__ out) {
    __shared__ float red[1024];
    const int tid = threadIdx.x;
    float s = 0.f;
    for (int r = tid; r < N_ROWS; r += 1024) s += g_rowsq[r];
    red[tid] = s;
    __syncthreads();
    #pragma unroll
    for (int st = 512; st > 0; st >>= 1) {
        if (tid < st) red[tid] += red[tid + st];
        __syncthreads();
    }
    if (tid == 0) {
        float mean = red[0] / (float)Q_ELEMS;
        out[Q_ELEMS] = 1.25f * mean;
        float L = (float)(g_maxidx + 1);
        float avg = 1.0f / L;
        out[Q_ELEMS + 1] = expf(-avg * logf(avg + 1e-10f));
    }
}

extern "C" void kernel_launch(void* const* d_in, const int* in_sizes, int n_in,
                              void* d_out, int out_size) {
    const float* x   = (const float*)d_in[0];
    const float* emb = (const float*)d_in[1];
    float* out = (float*)d_out;

    cudaFuncSetAttribute(vq_gemm_kernel, cudaFuncAttributeMaxDynamicSharedMemorySize, SM_TOTAL);

    convert_kernel<<<(N_ROWS + N_CODES) / 8, 256>>>(x, emb);
    vq_gemm_kernel<<<dim3(N_ROWS / BM, N_CODES / BN), 256, SM_TOTAL>>>();
    select_kernel<<<N_ROWS, 256>>>(x, emb, out);
    scalars_kernel<<<1, 1024>>>(out);
}

// round 12
// speedup vs baseline: 2.6882x; 1.0558x over previous
#include <cuda_runtime.h>
#include <cuda_fp16.h>
#include <cstdint>

// ---------------- problem constants ----------------
#define N_ROWS   16384
#define N_CODES  8192
#define DIM      512
#define Q_ELEMS  (N_ROWS * DIM)

// ---------------- GEMM tiling (fp16 in, fp16 accum) ----------------
#define BM 128
#define BN 128
#define KC 64                 // K elems per stage = 128 B per row
#define NSTAGES (DIM / KC)    // 8
#define CH 8                  // codes per argmin chunk
#define NCH (N_CODES / CH)    // 1024 chunk-mins per row
#define EPS 4.0e-4f
#define MAXCAND 64            // max candidate chunks per row

// dynamic smem: 3 stages x (A 16KB + B 16KB) = 98304; enorm after
#define STG_BYTES 32768
#define SM_BOFF   16384
#define SM_ENORM  98304
#define SM_TOTAL  (98304 + 512)

#define NPART 64              // scalar reduction partials

// ---------------- scratch (device globals; no allocation allowed) ----------------
__device__ __align__(256) __half g_hx[(size_t)N_ROWS * DIM];
__device__ __align__(256) __half g_he[(size_t)N_CODES * DIM];
__device__ float  g_xnorm[N_ROWS];
__device__ float  g_enorm[N_CODES];
__device__ __align__(16) __half g_cmin[(size_t)N_ROWS * NCH];   // d~ chunk mins, fp16
__device__ float  g_rowsq[N_ROWS];
__device__ float  g_part[NPART];
__device__ int    g_maxidx;

// ---------------- PTX helpers ----------------
__device__ __forceinline__ uint32_t smem_u32(const void* p) {
    uint32_t a;
    asm("{ .reg .u64 t; cvta.to.shared.u64 t, %1; cvt.u32.u64 %0, t; }"
        : "=r"(a) : "l"(p));
    return a;
}
__device__ __forceinline__ void cp16(uint32_t dst, const void* src) {
    asm volatile("cp.async.cg.shared.global [%0], [%1], 16;" :: "r"(dst), "l"(src) : "memory");
}
#define CP_COMMIT() asm volatile("cp.async.commit_group;" ::: "memory")
#define CP_WAIT(n)  asm volatile("cp.async.wait_group %0;" :: "n"(n) : "memory")

#define SWZ(b) ((b) ^ (((b) >> 3) & 0x70))

__device__ __forceinline__ void ldsm4(uint32_t* r, uint32_t addr) {
    asm volatile("ldmatrix.sync.aligned.m8n8.x4.shared.b16 {%0,%1,%2,%3}, [%4];"
                 : "=r"(r[0]), "=r"(r[1]), "=r"(r[2]), "=r"(r[3]) : "r"(addr));
}
// fp16 in, fp16 accum: C/D are 2 b32 regs (4 halves)
__device__ __forceinline__ void mma16816_h(uint32_t* c, const uint32_t* a, const uint32_t* b) {
    asm volatile(
        "mma.sync.aligned.m16n8k16.row.col.f16.f16.f16.f16 "
        "{%0,%1}, {%2,%3,%4,%5}, {%6,%7}, {%0,%1};"
        : "+r"(c[0]), "+r"(c[1])
        : "r"(a[0]), "r"(a[1]), "r"(a[2]), "r"(a[3]), "r"(b[0]), "r"(b[1]));
}

// ---------------- kernels ----------------

// one warp per row: fp32 norm + fp16 convert (block 0 also resets g_maxidx)
__global__ void convert_kernel(const float* __restrict__ x, const float* __restrict__ emb) {
    if (blockIdx.x == 0 && threadIdx.x == 0) g_maxidx = 0;
    int warp = (blockIdx.x * blockDim.x + threadIdx.x) >> 5;
    int lane = threadIdx.x & 31;
    const float* src; __half* dst; float* nrm; int row;
    if (warp < N_ROWS) { src = x; dst = g_hx; nrm = g_xnorm; row = warp; }
    else               { src = emb; dst = g_he; nrm = g_enorm; row = warp - N_ROWS; }
    const float4* p = reinterpret_cast<const float4*>(src + (size_t)row * DIM);
    uint2* o = reinterpret_cast<uint2*>(dst + (size_t)row * DIM);
    float s = 0.f;
    #pragma unroll
    for (int c = lane; c < DIM / 4; c += 32) {
        float4 v = p[c];
        s += v.x * v.x + v.y * v.y + v.z * v.z + v.w * v.w;
        __half2 lo = __floats2half2_rn(v.x, v.y);
        __half2 hi = __floats2half2_rn(v.z, v.w);
        uint2 u;
        u.x = *reinterpret_cast<unsigned*>(&lo);
        u.y = *reinterpret_cast<unsigned*>(&hi);
        o[c] = u;
    }
    #pragma unroll
    for (int off = 16; off; off >>= 1) s += __shfl_xor_sync(0xffffffffu, s, off);
    if (lane == 0) nrm[row] = s;
}

// fp16 HMMA GEMM: 128x128xK512 per CTA, 256 thr, 3-stage cp.async, ONE sync/stage.
// Epilogue: d~ = enorm - 2*dot, per-row min over 8-code chunks -> g_cmin (fp16).
__global__ void __launch_bounds__(256, 2) vq_gemm_kernel() {
    extern __shared__ __align__(1024) char smem[];
    const int tid = threadIdx.x;
    const int w = tid >> 5, l = tid & 31;
    const int rowBase = blockIdx.x * BM;
    const int cb = blockIdx.y * BN;
    const uint32_t sb = smem_u32(smem);
    float* senorm = reinterpret_cast<float*>(smem + SM_ENORM);

    if (tid < BN) senorm[tid] = g_enorm[cb + tid];

    // warp layout: 2 (M) x 4 (N); warp tile 64 x 32
    const int m0 = (w >> 2) * 64;
    const int n0 = (w & 3) * 32;
    const int aRowLane = l & 15;
    const int aChunkHi = l >> 4;
    const int bRowLane = ((l >> 4) & 1) * 8 + (l & 7);
    const int bChunkHi = (l >> 3) & 1;

    uint32_t c[4][4][2];
    #pragma unroll
    for (int mt = 0; mt < 4; mt++)
        #pragma unroll
        for (int nt = 0; nt < 4; nt++) { c[mt][nt][0] = 0u; c[mt][nt][1] = 0u; }

    auto load_stage = [&](int kc, int s) {
        const int kb = kc * KC;
        const uint32_t stg = sb + (uint32_t)s * STG_BYTES;
        #pragma unroll
        for (int q = 0; q < 4; q++) {
            int t = tid + q * 256;
            int r = t >> 3, ch = t & 7;
            cp16(stg + SWZ((uint32_t)(r * 128 + ch * 16)),
                 g_hx + (size_t)(rowBase + r) * DIM + kb + ch * 8);
        }
        #pragma unroll
        for (int q = 0; q < 4; q++) {
            int t = tid + q * 256;
            int r = t >> 3, ch = t & 7;
            cp16(stg + SM_BOFF + SWZ((uint32_t)(r * 128 + ch * 16)),
                 g_he + (size_t)(cb + r) * DIM + kb + ch * 8);
        }
        CP_COMMIT();
    };

    load_stage(0, 0);
    load_stage(1, 1);

    #pragma unroll
    for (int i = 0; i < NSTAGES; i++) {
        if (i < NSTAGES - 1) CP_WAIT(1); else CP_WAIT(0);
        __syncthreads();
        if (i + 2 < NSTAGES) load_stage(i + 2, (i + 2) % 3);
        const uint32_t aStg = sb + (uint32_t)(i % 3) * STG_BYTES;
        const uint32_t bStg = aStg + SM_BOFF;
        #pragma unroll
        for (int ks = 0; ks < 4; ks++) {
            uint32_t a[4][4], b[4][2];
            #pragma unroll
            for (int mt = 0; mt < 4; mt++) {
                uint32_t off = (uint32_t)((m0 + mt * 16 + aRowLane) * 128
                                          + (ks * 2 + aChunkHi) * 16);
                ldsm4(a[mt], aStg + SWZ(off));
            }
            #pragma unroll
            for (int nt2 = 0; nt2 < 2; nt2++) {
                uint32_t r4[4];
                uint32_t off = (uint32_t)((n0 + nt2 * 16 + bRowLane) * 128
                                          + (ks * 2 + bChunkHi) * 16);
                ldsm4(r4, bStg + SWZ(off));
                b[nt2 * 2][0] = r4[0]; b[nt2 * 2][1] = r4[1];
                b[nt2 * 2 + 1][0] = r4[2]; b[nt2 * 2 + 1][1] = r4[3];
            }
            #pragma unroll
            for (int mt = 0; mt < 4; mt++)
                #pragma unroll
                for (int nt = 0; nt < 4; nt++)
                    mma16816_h(c[mt][nt], a[mt], b[nt]);
        }
    }

    // ---- epilogue: chunk (8-code) mins -> smem staging -> coalesced fp16 gmem
    __syncthreads();
    float* sbuf = reinterpret_cast<float*>(smem);   // [128][20]

    #pragma unroll
    for (int mt = 0; mt < 4; mt++) {
        #pragma unroll
        for (int nt = 0; nt < 4; nt++) {
            const int colBase = n0 + nt * 8 + (l & 3) * 2;
            float en0 = senorm[colBase], en1 = senorm[colBase + 1];
            __half2 h0 = *reinterpret_cast<__half2*>(&c[mt][nt][0]);  // row r
            __half2 h1 = *reinterpret_cast<__half2*>(&c[mt][nt][1]);  // row r+8
            float v0 = fminf(en0 - 2.0f * __low2float(h0), en1 - 2.0f * __high2float(h0));
            float v1 = fminf(en0 - 2.0f * __low2float(h1), en1 - 2.0f * __high2float(h1));
            #pragma unroll
            for (int off = 1; off <= 2; off <<= 1) {
                v0 = fminf(v0, __shfl_xor_sync(0xffffffffu, v0, off));
                v1 = fminf(v1, __shfl_xor_sync(0xffffffffu, v1, off));
            }
            if ((l & 3) == 0) {
                int rloc = m0 + mt * 16 + (l >> 2);
                int chLoc = (w & 3) * 4 + nt;
                sbuf[rloc * 20 + chLoc] = v0;
                sbuf[(rloc + 8) * 20 + chLoc] = v1;
            }
        }
    }
    __syncthreads();
    {
        int row = tid >> 1, half = tid & 1;
        const float* s = &sbuf[row * 20 + half * 8];
        __half2 p0 = __floats2half2_rn(s[0], s[1]);
        __half2 p1 = __floats2half2_rn(s[2], s[3]);
        __half2 p2 = __floats2half2_rn(s[4], s[5]);
        __half2 p3 = __floats2half2_rn(s[6], s[7]);
        uint4 o;
        o.x = *reinterpret_cast<unsigned*>(&p0);
        o.y = *reinterpret_cast<unsigned*>(&p1);
        o.z = *reinterpret_cast<unsigned*>(&p2);
        o.w = *reinterpret_cast<unsigned*>(&p3);
        __half* dst = &g_cmin[(size_t)(blockIdx.x * BM + row) * NCH + blockIdx.y * 16 + half * 8];
        *reinterpret_cast<uint4*>(dst) = o;
    }
}

// block-per-row fused select, 128 threads (higher row concurrency):
// scan cmin row -> threshold -> exact fp32 rescore (packed u64 keys = exact
// first-index ties) -> fused gather + straight-through + rowsq.
__global__ void __launch_bounds__(128) select_kernel(const float* __restrict__ x,
                                                     const float* __restrict__ emb,
                                                     float* __restrict__ out) {
    __shared__ __align__(16) float sx[DIM];
    __shared__ float sred[4];
    __shared__ int   slist[MAXCAND];
    __shared__ int   scount;
    __shared__ unsigned long long skey[MAXCAND * CH];
    __shared__ int   sbesti;

    const int row = blockIdx.x;
    const int tid = threadIdx.x, w = tid >> 5, l = tid & 31;

    reinterpret_cast<float4*>(sx)[tid] =
        reinterpret_cast<const float4*>(x + (size_t)row * DIM)[tid];
    if (tid == 0) scount = 0;

    // scan: each thread holds 8 chunk-mins (uint4 = 8 halves), coalesced 2KB row
    uint4 u = reinterpret_cast<const uint4*>(&g_cmin[(size_t)row * NCH])[tid];
    float2 f0 = __half22float2(*reinterpret_cast<__half2*>(&u.x));
    float2 f1 = __half22float2(*reinterpret_cast<__half2*>(&u.y));
    float2 f2 = __half22float2(*reinterpret_cast<__half2*>(&u.z));
    float2 f3 = __half22float2(*reinterpret_cast<__half2*>(&u.w));
    float fv[8] = {f0.x, f0.y, f1.x, f1.y, f2.x, f2.y, f3.x, f3.y};
    float lmin = 3.4028235e38f;
    #pragma unroll
    for (int e = 0; e < 8; e++) lmin = fminf(lmin, fv[e]);
    #pragma unroll
    for (int off = 16; off; off >>= 1) lmin = fminf(lmin, __shfl_xor_sync(0xffffffffu, lmin, off));
    if (l == 0) sred[w] = lmin;
    __syncthreads();
    const float thr = fminf(fminf(sred[0], sred[1]), fminf(sred[2], sred[3])) + EPS;

    #pragma unroll
    for (int e = 0; e < 8; e++) {
        if (fv[e] <= thr) {
            int p = atomicAdd(&scount, 1);
            if (p < MAXCAND) slist[p] = tid * 8 + e;   // unordered is fine (key-min)
        }
    }
    __syncthreads();
    const int count = min(scount, MAXCAND);
    const int ncodes = count * CH;
    const float xn = g_xnorm[row];

    // flat-parallel exact fp32 rescore: warp w handles codes w, w+4, ...
    for (int k = w; k < ncodes; k += 4) {
        const int code = slist[k >> 3] * CH + (k & 7);
        const float4* e4 = reinterpret_cast<const float4*>(emb + (size_t)code * DIM);
        const float4* xs = reinterpret_cast<const float4*>(sx);
        float acc = 0.f;
        #pragma unroll
        for (int t = 0; t < 4; t++) {
            float4 ev = e4[l + 32 * t];
            float4 xv = xs[l + 32 * t];
            acc = fmaf(ev.x, xv.x, acc);
            acc = fmaf(ev.y, xv.y, acc);
            acc = fmaf(ev.z, xv.z, acc);
            acc = fmaf(ev.w, xv.w, acc);
        }
        #pragma unroll
        for (int off = 16; off; off >>= 1) acc += __shfl_xor_sync(0xffffffffu, acc, off);
        if (l == 0) {
            float d = __fsub_rn(__fadd_rn(xn, g_enorm[code]), 2.0f * acc);
            // d > 0 (distances ~512): float bits are order-preserving
            skey[k] = ((unsigned long long)__float_as_uint(d) << 32) | (unsigned)code;
        }
    }
    __syncthreads();

    if (w == 0) {
        unsigned long long best = 0xffffffffffffffffull;
        for (int k = l; k < ncodes; k += 32) best = min(best, skey[k]);
        #pragma unroll
        for (int off = 16; off; off >>= 1) {
            unsigned long long o = __shfl_xor_sync(0xffffffffu, best, off);
            best = min(best, o);
        }
        if (l == 0) {
            int bi = (int)(best & 0xffffffffu);
            sbesti = bi;
            out[Q_ELEMS + 2 + row] = (float)bi;
            atomicMax(&g_maxidx, bi);
        }
    }
    __syncthreads();
    const int idx = sbesti;

    // fused gather + straight-through + rowsq (float4 per thread)
    float4 qv = reinterpret_cast<const float4*>(emb + (size_t)idx * DIM)[tid];
    float4 xv = reinterpret_cast<const float4*>(sx)[tid];
    float4 ov;
    float d0 = __fsub_rn(qv.x, xv.x); ov.x = __fadd_rn(xv.x, d0);
    float d1 = __fsub_rn(qv.y, xv.y); ov.y = __fadd_rn(xv.y, d1);
    float d2 = __fsub_rn(qv.z, xv.z); ov.z = __fadd_rn(xv.z, d2);
    float d3 = __fsub_rn(qv.w, xv.w); ov.w = __fadd_rn(xv.w, d3);
    reinterpret_cast<float4*>(out + (size_t)row * DIM)[tid] = ov;
    float ss = (d0 * d0 + d1 * d1) + (d2 * d2 + d3 * d3);
    #pragma unroll
    for (int off = 16; off; off >>= 1) ss += __shfl_xor_sync(0xffffffffu, ss, off);
    if (l == 0) sred[w] = ss;
    __syncthreads();
    if (tid == 0)
        g_rowsq[row] = (sred[0] + sred[1]) + (sred[2] + sred[3]);
}

// stage 1: 64 blocks x 256 threads, each reduces a fixed 256-row slice (deterministic)
__global__ void scalars_partial_kernel() {
    __shared__ float red[8];
    const int tid = threadIdx.x, w = tid >> 5, l = tid & 31;
    float s = g_rowsq[blockIdx.x * 256 + tid];
    #pragma unroll
    for (int off = 16; off; off >>= 1) s += __shfl_xor_sync(0xffffffffu, s, off);
    if (l == 0) red[w] = s;
    __syncthreads();
    if (tid == 0) {
        float t = 0.f;
        #pragma unroll
        for (int ww = 0; ww < 8; ww++) t += red[ww];
        g_part[blockIdx.x] = t;
    }
}

// stage 2: one warp finishes, fixed order
__global__ void scalars_final_kernel(float* __restrict__ out) {
    const int l = threadIdx.x;
    float s = g_part[l] + g_part[l + 32];
    #pragma unroll
    for (int off = 16; off; off >>= 1) s += __shfl_xor_sync(0xffffffffu, s, off);
    if (l == 0) {
        float mean = s / (float)Q_ELEMS;
        out[Q_ELEMS] = 1.25f * mean;
        float L = (float)(g_maxidx + 1);
        float avg = 1.0f / L;
        out[Q_ELEMS + 1] = expf(-avg * logf(avg + 1e-10f));
    }
}

extern "C" void kernel_launch(void* const* d_in, const int* in_sizes, int n_in,
                              void* d_out, int out_size) {
    const float* x   = (const float*)d_in[0];
    const float* emb = (const float*)d_in[1];
    float* out = (float*)d_out;

    cudaFuncSetAttribute(vq_gemm_kernel, cudaFuncAttributeMaxDynamicSharedMemorySize, SM_TOTAL);

    convert_kernel<<<(N_ROWS + N_CODES) / 8, 256>>>(x, emb);
    vq_gemm_kernel<<<dim3(N_ROWS / BM, N_CODES / BN), 256, SM_TOTAL>>>();
    select_kernel<<<N_ROWS, 128>>>(x, emb, out);
    scalars_partial_kernel<<<NPART, 256>>>();
    scalars_final_kernel<<<1, 32>>>(out);
}

// round 13
// speedup vs baseline: 2.7092x; 1.0078x over previous
#include <cuda_runtime.h>
#include <cuda_fp16.h>
#include <cstdint>

// ---------------- problem constants ----------------
#define N_ROWS   16384
#define N_CODES  8192
#define DIM      512
#define Q_ELEMS  (N_ROWS * DIM)

// ---------------- GEMM tiling (fp16 in, fp16 accum) ----------------
#define BM 128
#define BN 128
#define KC 64                 // K elems per stage = 128 B per row
#define NSTAGES (DIM / KC)    // 8
#define CH 8                  // codes per argmin chunk
#define NCH (N_CODES / CH)    // 1024 chunk-mins per row
#define EPS 4.0e-4f
#define MAXCAND 64            // max candidate chunks per row

// dynamic smem: 3 stages x (A 16KB + B 16KB) = 98304; enorm after
#define STG_BYTES 32768
#define SM_BOFF   16384
#define SM_ENORM  98304
#define SM_TOTAL  (98304 + 512)

#define NPART 64              // scalar reduction partials

// ---------------- scratch (device globals; no allocation allowed) ----------------
__device__ __align__(256) __half g_hx[(size_t)N_ROWS * DIM];
__device__ __align__(256) __half g_he[(size_t)N_CODES * DIM];
__device__ float  g_xnorm[N_ROWS];
__device__ float  g_enorm[N_CODES];
__device__ __align__(16) __half g_cmin[(size_t)N_ROWS * NCH];   // d~ chunk mins, fp16
__device__ float  g_rowsq[N_ROWS];
__device__ float  g_part[NPART];
__device__ int    g_maxidx;

// ---------------- PTX helpers ----------------
__device__ __forceinline__ uint32_t smem_u32(const void* p) {
    uint32_t a;
    asm("{ .reg .u64 t; cvta.to.shared.u64 t, %1; cvt.u32.u64 %0, t; }"
        : "=r"(a) : "l"(p));
    return a;
}
__device__ __forceinline__ void cp16(uint32_t dst, const void* src) {
    asm volatile("cp.async.cg.shared.global [%0], [%1], 16;" :: "r"(dst), "l"(src) : "memory");
}
__device__ __forceinline__ void cp4(uint32_t dst, const void* src) {
    asm volatile("cp.async.ca.shared.global [%0], [%1], 4;" :: "r"(dst), "l"(src) : "memory");
}
#define CP_COMMIT() asm volatile("cp.async.commit_group;" ::: "memory")
#define CP_WAIT(n)  asm volatile("cp.async.wait_group %0;" :: "n"(n) : "memory")

#define SWZ(b) ((b) ^ (((b) >> 3) & 0x70))

__device__ __forceinline__ void ldsm4(uint32_t* r, uint32_t addr) {
    asm volatile("ldmatrix.sync.aligned.m8n8.x4.shared.b16 {%0,%1,%2,%3}, [%4];"
                 : "=r"(r[0]), "=r"(r[1]), "=r"(r[2]), "=r"(r[3]) : "r"(addr));
}
// fp16 in, fp16 accum: C/D are 2 b32 regs (4 halves)
__device__ __forceinline__ void mma16816_h(uint32_t* c, const uint32_t* a, const uint32_t* b) {
    asm volatile(
        "mma.sync.aligned.m16n8k16.row.col.f16.f16.f16.f16 "
        "{%0,%1}, {%2,%3,%4,%5}, {%6,%7}, {%0,%1};"
        : "+r"(c[0]), "+r"(c[1])
        : "r"(a[0]), "r"(a[1]), "r"(a[2]), "r"(a[3]), "r"(b[0]), "r"(b[1]));
}

// ---------------- kernels ----------------

// one warp per row: fp32 norm + fp16 convert (block 0 also resets g_maxidx)
__global__ void convert_kernel(const float* __restrict__ x, const float* __restrict__ emb) {
    if (blockIdx.x == 0 && threadIdx.x == 0) g_maxidx = 0;
    int warp = (blockIdx.x * blockDim.x + threadIdx.x) >> 5;
    int lane = threadIdx.x & 31;
    const float* src; __half* dst; float* nrm; int row;
    if (warp < N_ROWS) { src = x; dst = g_hx; nrm = g_xnorm; row = warp; }
    else               { src = emb; dst = g_he; nrm = g_enorm; row = warp - N_ROWS; }
    const float4* p = reinterpret_cast<const float4*>(src + (size_t)row * DIM);
    uint2* o = reinterpret_cast<uint2*>(dst + (size_t)row * DIM);
    float s = 0.f;
    #pragma unroll
    for (int c = lane; c < DIM / 4; c += 32) {
        float4 v = p[c];
        s += v.x * v.x + v.y * v.y + v.z * v.z + v.w * v.w;
        __half2 lo = __floats2half2_rn(v.x, v.y);
        __half2 hi = __floats2half2_rn(v.z, v.w);
        uint2 u;
        u.x = *reinterpret_cast<unsigned*>(&lo);
        u.y = *reinterpret_cast<unsigned*>(&hi);
        o[c] = u;
    }
    #pragma unroll
    for (int off = 16; off; off >>= 1) s += __shfl_xor_sync(0xffffffffu, s, off);
    if (lane == 0) nrm[row] = s;
}

// fp16 HMMA GEMM: 128x128xK512 per CTA, 256 thr, 3-stage cp.async, ONE sync/stage.
// Epilogue: d~ = enorm - 2*dot, per-row min over 8-code chunks -> g_cmin (fp16).
__global__ void __launch_bounds__(256, 2) vq_gemm_kernel() {
    extern __shared__ __align__(1024) char smem[];
    const int tid = threadIdx.x;
    const int w = tid >> 5, l = tid & 31;
    const int rowBase = blockIdx.x * BM;
    const int cb = blockIdx.y * BN;
    const uint32_t sb = smem_u32(smem);
    float* senorm = reinterpret_cast<float*>(smem + SM_ENORM);

    // enorm tile via cp.async, joins stage-0 commit group (needed only in epilogue)
    if (tid < BN) cp4(sb + SM_ENORM + tid * 4u, g_enorm + cb + tid);

    // warp layout: 2 (M) x 4 (N); warp tile 64 x 32
    const int m0 = (w >> 2) * 64;
    const int n0 = (w & 3) * 32;
    const int aRowLane = l & 15;
    const int aChunkHi = l >> 4;
    const int bRowLane = ((l >> 4) & 1) * 8 + (l & 7);
    const int bChunkHi = (l >> 3) & 1;

    uint32_t c[4][4][2];
    #pragma unroll
    for (int mt = 0; mt < 4; mt++)
        #pragma unroll
        for (int nt = 0; nt < 4; nt++) { c[mt][nt][0] = 0u; c[mt][nt][1] = 0u; }

    auto load_stage = [&](int kc, int s) {
        const int kb = kc * KC;
        const uint32_t stg = sb + (uint32_t)s * STG_BYTES;
        #pragma unroll
        for (int q = 0; q < 4; q++) {
            int t = tid + q * 256;
            int r = t >> 3, ch = t & 7;
            cp16(stg + SWZ((uint32_t)(r * 128 + ch * 16)),
                 g_hx + (size_t)(rowBase + r) * DIM + kb + ch * 8);
        }
        #pragma unroll
        for (int q = 0; q < 4; q++) {
            int t = tid + q * 256;
            int r = t >> 3, ch = t & 7;
            cp16(stg + SM_BOFF + SWZ((uint32_t)(r * 128 + ch * 16)),
                 g_he + (size_t)(cb + r) * DIM + kb + ch * 8);
        }
        CP_COMMIT();
    };

    load_stage(0, 0);
    load_stage(1, 1);

    #pragma unroll
    for (int i = 0; i < NSTAGES; i++) {
        if (i < NSTAGES - 1) CP_WAIT(1); else CP_WAIT(0);
        __syncthreads();
        if (i + 2 < NSTAGES) load_stage(i + 2, (i + 2) % 3);
        const uint32_t aStg = sb + (uint32_t)(i % 3) * STG_BYTES;
        const uint32_t bStg = aStg + SM_BOFF;
        #pragma unroll
        for (int ks = 0; ks < 4; ks++) {
            uint32_t a[4][4], b[4][2];
            #pragma unroll
            for (int mt = 0; mt < 4; mt++) {
                uint32_t off = (uint32_t)((m0 + mt * 16 + aRowLane) * 128
                                          + (ks * 2 + aChunkHi) * 16);
                ldsm4(a[mt], aStg + SWZ(off));
            }
            #pragma unroll
            for (int nt2 = 0; nt2 < 2; nt2++) {
                uint32_t r4[4];
                uint32_t off = (uint32_t)((n0 + nt2 * 16 + bRowLane) * 128
                                          + (ks * 2 + bChunkHi) * 16);
                ldsm4(r4, bStg + SWZ(off));
                b[nt2 * 2][0] = r4[0]; b[nt2 * 2][1] = r4[1];
                b[nt2 * 2 + 1][0] = r4[2]; b[nt2 * 2 + 1][1] = r4[3];
            }
            #pragma unroll
            for (int mt = 0; mt < 4; mt++)
                #pragma unroll
                for (int nt = 0; nt < 4; nt++)
                    mma16816_h(c[mt][nt], a[mt], b[nt]);
        }
    }

    // ---- epilogue: chunk (8-code) mins -> smem staging -> coalesced fp16 gmem
    __syncthreads();
    float* sbuf = reinterpret_cast<float*>(smem);   // [128][20]

    #pragma unroll
    for (int mt = 0; mt < 4; mt++) {
        #pragma unroll
        for (int nt = 0; nt < 4; nt++) {
            const int colBase = n0 + nt * 8 + (l & 3) * 2;
            float en0 = senorm[colBase], en1 = senorm[colBase + 1];
            __half2 h0 = *reinterpret_cast<__half2*>(&c[mt][nt][0]);  // row r
            __half2 h1 = *reinterpret_cast<__half2*>(&c[mt][nt][1]);  // row r+8
            float v0 = fminf(en0 - 2.0f * __low2float(h0), en1 - 2.0f * __high2float(h0));
            float v1 = fminf(en0 - 2.0f * __low2float(h1), en1 - 2.0f * __high2float(h1));
            #pragma unroll
            for (int off = 1; off <= 2; off <<= 1) {
                v0 = fminf(v0, __shfl_xor_sync(0xffffffffu, v0, off));
                v1 = fminf(v1, __shfl_xor_sync(0xffffffffu, v1, off));
            }
            if ((l & 3) == 0) {
                int rloc = m0 + mt * 16 + (l >> 2);
                int chLoc = (w & 3) * 4 + nt;
                sbuf[rloc * 20 + chLoc] = v0;
                sbuf[(rloc + 8) * 20 + chLoc] = v1;
            }
        }
    }
    __syncthreads();
    {
        int row = tid >> 1, half = tid & 1;
        const float* s = &sbuf[row * 20 + half * 8];
        __half2 p0 = __floats2half2_rn(s[0], s[1]);
        __half2 p1 = __floats2half2_rn(s[2], s[3]);
        __half2 p2 = __floats2half2_rn(s[4], s[5]);
        __half2 p3 = __floats2half2_rn(s[6], s[7]);
        uint4 o;
        o.x = *reinterpret_cast<unsigned*>(&p0);
        o.y = *reinterpret_cast<unsigned*>(&p1);
        o.z = *reinterpret_cast<unsigned*>(&p2);
        o.w = *reinterpret_cast<unsigned*>(&p3);
        __half* dst = &g_cmin[(size_t)(blockIdx.x * BM + row) * NCH + blockIdx.y * 16 + half * 8];
        *reinterpret_cast<uint4*>(dst) = o;
    }
}

// block-per-row fused select, 128 threads. x-row prefetched via cp.async while
// the cmin scan runs; per-warp register-held best keys (exact first-index ties).
__global__ void __launch_bounds__(128) select_kernel(const float* __restrict__ x,
                                                     const float* __restrict__ emb,
                                                     float* __restrict__ out) {
    __shared__ __align__(16) float sx[DIM];
    __shared__ float sred[4];
    __shared__ int   slist[MAXCAND];
    __shared__ int   scount;
    __shared__ unsigned long long swkey[4];
    __shared__ int   sbesti;

    const int row = blockIdx.x;
    const int tid = threadIdx.x, w = tid >> 5, l = tid & 31;
    const uint32_t sxb = smem_u32(sx);

    // prefetch x row (overlaps with cmin scan below)
    cp16(sxb + tid * 16u, x + (size_t)row * DIM + tid * 4);
    CP_COMMIT();
    if (tid == 0) scount = 0;

    // scan: each thread holds 8 chunk-mins (uint4 = 8 halves), coalesced 2KB row
    uint4 u = reinterpret_cast<const uint4*>(&g_cmin[(size_t)row * NCH])[tid];
    float2 f0 = __half22float2(*reinterpret_cast<__half2*>(&u.x));
    float2 f1 = __half22float2(*reinterpret_cast<__half2*>(&u.y));
    float2 f2 = __half22float2(*reinterpret_cast<__half2*>(&u.z));
    float2 f3 = __half22float2(*reinterpret_cast<__half2*>(&u.w));
    float fv[8] = {f0.x, f0.y, f1.x, f1.y, f2.x, f2.y, f3.x, f3.y};
    float lmin = 3.4028235e38f;
    #pragma unroll
    for (int e = 0; e < 8; e++) lmin = fminf(lmin, fv[e]);
    #pragma unroll
    for (int off = 16; off; off >>= 1) lmin = fminf(lmin, __shfl_xor_sync(0xffffffffu, lmin, off));
    if (l == 0) sred[w] = lmin;
    __syncthreads();
    const float thr = fminf(fminf(sred[0], sred[1]), fminf(sred[2], sred[3])) + EPS;

    #pragma unroll
    for (int e = 0; e < 8; e++) {
        if (fv[e] <= thr) {
            int p = atomicAdd(&scount, 1);
            if (p < MAXCAND) slist[p] = tid * 8 + e;   // unordered is fine (key-min)
        }
    }
    CP_WAIT(0);                 // x row resident in sx
    __syncthreads();
    const int count = min(scount, MAXCAND);
    const int ncodes = count * CH;
    const float xn = g_xnorm[row];

    // flat-parallel exact fp32 rescore: warp w handles codes w, w+4, ...
    unsigned long long wbest = 0xffffffffffffffffull;
    for (int k = w; k < ncodes; k += 4) {
        const int code = slist[k >> 3] * CH + (k & 7);
        const float4* e4 = reinterpret_cast<const float4*>(emb + (size_t)code * DIM);
        const float4* xs = reinterpret_cast<const float4*>(sx);
        float acc = 0.f;
        #pragma unroll
        for (int t = 0; t < 4; t++) {
            float4 ev = e4[l + 32 * t];
            float4 xv = xs[l + 32 * t];
            acc = fmaf(ev.x, xv.x, acc);
            acc = fmaf(ev.y, xv.y, acc);
            acc = fmaf(ev.z, xv.z, acc);
            acc = fmaf(ev.w, xv.w, acc);
        }
        #pragma unroll
        for (int off = 16; off; off >>= 1) acc += __shfl_xor_sync(0xffffffffu, acc, off);
        if (l == 0) {
            float d = __fsub_rn(__fadd_rn(xn, g_enorm[code]), 2.0f * acc);
            // d > 0 (distances ~512): float bits are order-preserving
            unsigned long long key =
                ((unsigned long long)__float_as_uint(d) << 32) | (unsigned)code;
            wbest = min(wbest, key);
        }
    }
    if (l == 0) swkey[w] = wbest;
    __syncthreads();

    if (tid == 0) {
        unsigned long long best = min(min(swkey[0], swkey[1]), min(swkey[2], swkey[3]));
        int bi = (int)(best & 0xffffffffu);
        sbesti = bi;
        out[Q_ELEMS + 2 + row] = (float)bi;
        atomicMax(&g_maxidx, bi);
    }
    __syncthreads();
    const int idx = sbesti;

    // fused gather + straight-through + rowsq (float4 per thread)
    float4 qv = reinterpret_cast<const float4*>(emb + (size_t)idx * DIM)[tid];
    float4 xv = reinterpret_cast<const float4*>(sx)[tid];
    float4 ov;
    float d0 = __fsub_rn(qv.x, xv.x); ov.x = __fadd_rn(xv.x, d0);
    float d1 = __fsub_rn(qv.y, xv.y); ov.y = __fadd_rn(xv.y, d1);
    float d2 = __fsub_rn(qv.z, xv.z); ov.z = __fadd_rn(xv.z, d2);
    float d3 = __fsub_rn(qv.w, xv.w); ov.w = __fadd_rn(xv.w, d3);
    reinterpret_cast<float4*>(out + (size_t)row * DIM)[tid] = ov;
    float ss = (d0 * d0 + d1 * d1) + (d2 * d2 + d3 * d3);
    #pragma unroll
    for (int off = 16; off; off >>= 1) ss += __shfl_xor_sync(0xffffffffu, ss, off);
    if (l == 0) sred[w] = ss;
    __syncthreads();
    if (tid == 0)
        g_rowsq[row] = (sred[0] + sred[1]) + (sred[2] + sred[3]);
}

// stage 1: 64 blocks x 256 threads, each reduces a fixed 256-row slice (deterministic)
__global__ void scalars_partial_kernel() {
    __shared__ float red[8];
    const int tid = threadIdx.x, w = tid >> 5, l = tid & 31;
    float s = g_rowsq[blockIdx.x * 256 + tid];
    #pragma unroll
    for (int off = 16; off; off >>= 1) s += __shfl_xor_sync(0xffffffffu, s, off);
    if (l == 0) red[w] = s;
    __syncthreads();
    if (tid == 0) {
        float t = 0.f;
        #pragma unroll
        for (int ww = 0; ww < 8; ww++) t += red[ww];
        g_part[blockIdx.x] = t;
    }
}

// stage 2: one warp finishes, fixed order
__global__ void scalars_final_kernel(float* __restrict__ out) {
    const int l = threadIdx.x;
    float s = g_part[l] + g_part[l + 32];
    #pragma unroll
    for (int off = 16; off; off >>= 1) s += __shfl_xor_sync(0xffffffffu, s, off);
    if (l == 0) {
        float mean = s / (float)Q_ELEMS;
        out[Q_ELEMS] = 1.25f * mean;
        float L = (float)(g_maxidx + 1);
        float avg = 1.0f / L;
        out[Q_ELEMS + 1] = expf(-avg * logf(avg + 1e-10f));
    }
}

extern "C" void kernel_launch(void* const* d_in, const int* in_sizes, int n_in,
                              void* d_out, int out_size) {
    const float* x   = (const float*)d_in[0];
    const float* emb = (const float*)d_in[1];
    float* out = (float*)d_out;

    cudaFuncSetAttribute(vq_gemm_kernel, cudaFuncAttributeMaxDynamicSharedMemorySize, SM_TOTAL);

    convert_kernel<<<(N_ROWS + N_CODES) / 8, 256>>>(x, emb);
    vq_gemm_kernel<<<dim3(N_ROWS / BM, N_CODES / BN), 256, SM_TOTAL>>>();
    select_kernel<<<N_ROWS, 128>>>(x, emb, out);
    scalars_partial_kernel<<<NPART, 256>>>();
    scalars_final_kernel<<<1, 32>>>(out);
}

// round 14
// speedup vs baseline: 2.7268x; 1.0065x over previous
#include <cuda_runtime.h>
#include <cuda_fp16.h>
#include <cstdint>

// ---------------- problem constants ----------------
#define N_ROWS   16384
#define N_CODES  8192
#define DIM      512
#define Q_ELEMS  (N_ROWS * DIM)

// ---------------- GEMM tiling (fp16 in, fp16 accum) ----------------
#define BM 128
#define BN 128
#define KC 64                 // K elems per stage = 128 B per row
#define NSTAGES (DIM / KC)    // 8
#define CH 8                  // codes per argmin chunk
#define NCH (N_CODES / CH)    // 1024 chunk-mins per row
#define EPS 4.0e-4f
#define MAXCAND 64            // max candidate chunks per row

// dynamic smem: 3 stages x (A 16KB + B 16KB) = 98304; enorm after
#define STG_BYTES 32768
#define SM_BOFF   16384
#define SM_ENORM  98304
#define SM_TOTAL  (98304 + 512)

#define NPART 64              // scalar reduction partials

// ---------------- scratch (device globals; no allocation allowed) ----------------
__device__ __align__(256) __half g_hx[(size_t)N_ROWS * DIM];
__device__ __align__(256) __half g_he[(size_t)N_CODES * DIM];
__device__ float  g_xnorm[N_ROWS];
__device__ float  g_enorm[N_CODES];
__device__ __align__(16) __half g_cmin[(size_t)N_ROWS * NCH];   // d~ chunk mins, fp16
__device__ float  g_rowsq[N_ROWS];
__device__ float  g_part[NPART];
__device__ int    g_maxidx;

// ---------------- PTX helpers ----------------
__device__ __forceinline__ uint32_t smem_u32(const void* p) {
    uint32_t a;
    asm("{ .reg .u64 t; cvta.to.shared.u64 t, %1; cvt.u32.u64 %0, t; }"
        : "=r"(a) : "l"(p));
    return a;
}
__device__ __forceinline__ void cp16(uint32_t dst, const void* src) {
    asm volatile("cp.async.cg.shared.global [%0], [%1], 16;" :: "r"(dst), "l"(src) : "memory");
}
__device__ __forceinline__ void cp4(uint32_t dst, const void* src) {
    asm volatile("cp.async.ca.shared.global [%0], [%1], 4;" :: "r"(dst), "l"(src) : "memory");
}
#define CP_COMMIT() asm volatile("cp.async.commit_group;" ::: "memory")
#define CP_WAIT(n)  asm volatile("cp.async.wait_group %0;" :: "n"(n) : "memory")

#define SWZ(b) ((b) ^ (((b) >> 3) & 0x70))

__device__ __forceinline__ void ldsm4(uint32_t* r, uint32_t addr) {
    asm volatile("ldmatrix.sync.aligned.m8n8.x4.shared.b16 {%0,%1,%2,%3}, [%4];"
                 : "=r"(r[0]), "=r"(r[1]), "=r"(r[2]), "=r"(r[3]) : "r"(addr));
}
// fp16 in, fp16 accum: C/D are 2 b32 regs (4 halves)
__device__ __forceinline__ void mma16816_h(uint32_t* c, const uint32_t* a, const uint32_t* b) {
    asm volatile(
        "mma.sync.aligned.m16n8k16.row.col.f16.f16.f16.f16 "
        "{%0,%1}, {%2,%3,%4,%5}, {%6,%7}, {%0,%1};"
        : "+r"(c[0]), "+r"(c[1])
        : "r"(a[0]), "r"(a[1]), "r"(a[2]), "r"(a[3]), "r"(b[0]), "r"(b[1]));
}

// ---------------- kernels ----------------

// one warp per row: fp32 norm + fp16 convert (block 0 also resets g_maxidx)
__global__ void convert_kernel(const float* __restrict__ x, const float* __restrict__ emb) {
    if (blockIdx.x == 0 && threadIdx.x == 0) g_maxidx = 0;
    int warp = (blockIdx.x * blockDim.x + threadIdx.x) >> 5;
    int lane = threadIdx.x & 31;
    const float* src; __half* dst; float* nrm; int row;
    if (warp < N_ROWS) { src = x; dst = g_hx; nrm = g_xnorm; row = warp; }
    else               { src = emb; dst = g_he; nrm = g_enorm; row = warp - N_ROWS; }
    const float4* p = reinterpret_cast<const float4*>(src + (size_t)row * DIM);
    uint2* o = reinterpret_cast<uint2*>(dst + (size_t)row * DIM);
    float s = 0.f;
    #pragma unroll
    for (int c = lane; c < DIM / 4; c += 32) {
        float4 v = p[c];
        s += v.x * v.x + v.y * v.y + v.z * v.z + v.w * v.w;
        __half2 lo = __floats2half2_rn(v.x, v.y);
        __half2 hi = __floats2half2_rn(v.z, v.w);
        uint2 u;
        u.x = *reinterpret_cast<unsigned*>(&lo);
        u.y = *reinterpret_cast<unsigned*>(&hi);
        o[c] = u;
    }
    #pragma unroll
    for (int off = 16; off; off >>= 1) s += __shfl_xor_sync(0xffffffffu, s, off);
    if (lane == 0) nrm[row] = s;
}

// fp16 HMMA GEMM: 128x128xK512 per CTA, 256 thr, 3-stage cp.async, ONE sync/stage.
// Epilogue: d~ = enorm - 2*dot, per-row min over 8-code chunks -> g_cmin (fp16).
__global__ void __launch_bounds__(256, 2) vq_gemm_kernel() {
    extern __shared__ __align__(1024) char smem[];
    const int tid = threadIdx.x;
    const int w = tid >> 5, l = tid & 31;
    const int rowBase = blockIdx.x * BM;
    const int cb = blockIdx.y * BN;
    const uint32_t sb = smem_u32(smem);
    float* senorm = reinterpret_cast<float*>(smem + SM_ENORM);

    // enorm tile via cp.async, joins stage-0 commit group (needed only in epilogue)
    if (tid < BN) cp4(sb + SM_ENORM + tid * 4u, g_enorm + cb + tid);

    // warp layout: 2 (M) x 4 (N); warp tile 64 x 32
    const int m0 = (w >> 2) * 64;
    const int n0 = (w & 3) * 32;
    const int aRowLane = l & 15;
    const int aChunkHi = l >> 4;
    const int bRowLane = ((l >> 4) & 1) * 8 + (l & 7);
    const int bChunkHi = (l >> 3) & 1;

    uint32_t c[4][4][2];
    #pragma unroll
    for (int mt = 0; mt < 4; mt++)
        #pragma unroll
        for (int nt = 0; nt < 4; nt++) { c[mt][nt][0] = 0u; c[mt][nt][1] = 0u; }

    auto load_stage = [&](int kc, int s) {
        const int kb = kc * KC;
        const uint32_t stg = sb + (uint32_t)s * STG_BYTES;
        #pragma unroll
        for (int q = 0; q < 4; q++) {
            int t = tid + q * 256;
            int r = t >> 3, ch = t & 7;
            cp16(stg + SWZ((uint32_t)(r * 128 + ch * 16)),
                 g_hx + (size_t)(rowBase + r) * DIM + kb + ch * 8);
        }
        #pragma unroll
        for (int q = 0; q < 4; q++) {
            int t = tid + q * 256;
            int r = t >> 3, ch = t & 7;
            cp16(stg + SM_BOFF + SWZ((uint32_t)(r * 128 + ch * 16)),
                 g_he + (size_t)(cb + r) * DIM + kb + ch * 8);
        }
        CP_COMMIT();
    };

    load_stage(0, 0);
    load_stage(1, 1);

    #pragma unroll
    for (int i = 0; i < NSTAGES; i++) {
        if (i < NSTAGES - 1) CP_WAIT(1); else CP_WAIT(0);
        __syncthreads();
        if (i + 2 < NSTAGES) load_stage(i + 2, (i + 2) % 3);
        const uint32_t aStg = sb + (uint32_t)(i % 3) * STG_BYTES;
        const uint32_t bStg = aStg + SM_BOFF;
        #pragma unroll
        for (int ks = 0; ks < 4; ks++) {
            uint32_t a[4][4], b[4][2];
            #pragma unroll
            for (int mt = 0; mt < 4; mt++) {
                uint32_t off = (uint32_t)((m0 + mt * 16 + aRowLane) * 128
                                          + (ks * 2 + aChunkHi) * 16);
                ldsm4(a[mt], aStg + SWZ(off));
            }
            #pragma unroll
            for (int nt2 = 0; nt2 < 2; nt2++) {
                uint32_t r4[4];
                uint32_t off = (uint32_t)((n0 + nt2 * 16 + bRowLane) * 128
                                          + (ks * 2 + bChunkHi) * 16);
                ldsm4(r4, bStg + SWZ(off));
                b[nt2 * 2][0] = r4[0]; b[nt2 * 2][1] = r4[1];
                b[nt2 * 2 + 1][0] = r4[2]; b[nt2 * 2 + 1][1] = r4[3];
            }
            #pragma unroll
            for (int mt = 0; mt < 4; mt++)
                #pragma unroll
                for (int nt = 0; nt < 4; nt++)
                    mma16816_h(c[mt][nt], a[mt], b[nt]);
        }
    }

    // ---- epilogue: chunk (8-code) mins -> smem staging -> coalesced fp16 gmem
    __syncthreads();
    float* sbuf = reinterpret_cast<float*>(smem);   // [128][20]

    #pragma unroll
    for (int mt = 0; mt < 4; mt++) {
        #pragma unroll
        for (int nt = 0; nt < 4; nt++) {
            const int colBase = n0 + nt * 8 + (l & 3) * 2;
            float en0 = senorm[colBase], en1 = senorm[colBase + 1];
            __half2 h0 = *reinterpret_cast<__half2*>(&c[mt][nt][0]);  // row r
            __half2 h1 = *reinterpret_cast<__half2*>(&c[mt][nt][1]);  // row r+8
            float v0 = fminf(en0 - 2.0f * __low2float(h0), en1 - 2.0f * __high2float(h0));
            float v1 = fminf(en0 - 2.0f * __low2float(h1), en1 - 2.0f * __high2float(h1));
            #pragma unroll
            for (int off = 1; off <= 2; off <<= 1) {
                v0 = fminf(v0, __shfl_xor_sync(0xffffffffu, v0, off));
                v1 = fminf(v1, __shfl_xor_sync(0xffffffffu, v1, off));
            }
            if ((l & 3) == 0) {
                int rloc = m0 + mt * 16 + (l >> 2);
                int chLoc = (w & 3) * 4 + nt;
                sbuf[rloc * 20 + chLoc] = v0;
                sbuf[(rloc + 8) * 20 + chLoc] = v1;
            }
        }
    }
    __syncthreads();
    {
        int row = tid >> 1, half = tid & 1;
        const float* s = &sbuf[row * 20 + half * 8];
        __half2 p0 = __floats2half2_rn(s[0], s[1]);
        __half2 p1 = __floats2half2_rn(s[2], s[3]);
        __half2 p2 = __floats2half2_rn(s[4], s[5]);
        __half2 p3 = __floats2half2_rn(s[6], s[7]);
        uint4 o;
        o.x = *reinterpret_cast<unsigned*>(&p0);
        o.y = *reinterpret_cast<unsigned*>(&p1);
        o.z = *reinterpret_cast<unsigned*>(&p2);
        o.w = *reinterpret_cast<unsigned*>(&p3);
        __half* dst = &g_cmin[(size_t)(blockIdx.x * BM + row) * NCH + blockIdx.y * 16 + half * 8];
        *reinterpret_cast<uint4*>(dst) = o;
    }
}

// block-per-row fused select, 64 threads (2 warps) for 2x row concurrency.
// x-row prefetched via cp.async during the cmin scan; per-warp register-held
// best keys (packed u64 = exact first-index ties); fused gather/ST/rowsq.
__global__ void __launch_bounds__(64) select_kernel(const float* __restrict__ x,
                                                    const float* __restrict__ emb,
                                                    float* __restrict__ out) {
    __shared__ __align__(16) float sx[DIM];
    __shared__ float sred[2];
    __shared__ int   slist[MAXCAND];
    __shared__ int   scount;
    __shared__ unsigned long long swkey[2];
    __shared__ int   sbesti;

    const int row = blockIdx.x;
    const int tid = threadIdx.x, w = tid >> 5, l = tid & 31;
    const uint32_t sxb = smem_u32(sx);

    // prefetch x row: 2 x 16B per thread (overlaps with cmin scan below)
    cp16(sxb + tid * 16u, x + (size_t)row * DIM + tid * 4);
    cp16(sxb + (tid + 64) * 16u, x + (size_t)row * DIM + (tid + 64) * 4);
    CP_COMMIT();
    if (tid == 0) scount = 0;

    // scan: each thread holds 16 chunk-mins (2 x uint4), coalesced 2KB row
    const uint4* cm = reinterpret_cast<const uint4*>(&g_cmin[(size_t)row * NCH]);
    float fv[2][8];
    float lmin = 3.4028235e38f;
    #pragma unroll
    for (int p = 0; p < 2; p++) {
        uint4 u = cm[tid + p * 64];
        float2 f0 = __half22float2(*reinterpret_cast<__half2*>(&u.x));
        float2 f1 = __half22float2(*reinterpret_cast<__half2*>(&u.y));
        float2 f2 = __half22float2(*reinterpret_cast<__half2*>(&u.z));
        float2 f3 = __half22float2(*reinterpret_cast<__half2*>(&u.w));
        fv[p][0] = f0.x; fv[p][1] = f0.y; fv[p][2] = f1.x; fv[p][3] = f1.y;
        fv[p][4] = f2.x; fv[p][5] = f2.y; fv[p][6] = f3.x; fv[p][7] = f3.y;
        #pragma unroll
        for (int e = 0; e < 8; e++) lmin = fminf(lmin, fv[p][e]);
    }
    #pragma unroll
    for (int off = 16; off; off >>= 1) lmin = fminf(lmin, __shfl_xor_sync(0xffffffffu, lmin, off));
    if (l == 0) sred[w] = lmin;
    __syncthreads();
    const float thr = fminf(sred[0], sred[1]) + EPS;

    #pragma unroll
    for (int p = 0; p < 2; p++)
        #pragma unroll
        for (int e = 0; e < 8; e++) {
            if (fv[p][e] <= thr) {
                int q = atomicAdd(&scount, 1);
                if (q < MAXCAND) slist[q] = (tid + p * 64) * 8 + e;  // unordered OK (key-min)
            }
        }
    CP_WAIT(0);                 // x row resident in sx
    __syncthreads();
    const int count = min(scount, MAXCAND);
    const int ncodes = count * CH;
    const float xn = g_xnorm[row];

    // flat-parallel exact fp32 rescore: warp w handles codes w, w+2, ...
    unsigned long long wbest = 0xffffffffffffffffull;
    for (int k = w; k < ncodes; k += 2) {
        const int code = slist[k >> 3] * CH + (k & 7);
        const float4* e4 = reinterpret_cast<const float4*>(emb + (size_t)code * DIM);
        const float4* xs = reinterpret_cast<const float4*>(sx);
        float acc = 0.f;
        #pragma unroll
        for (int t = 0; t < 4; t++) {
            float4 ev = e4[l + 32 * t];
            float4 xv = xs[l + 32 * t];
            acc = fmaf(ev.x, xv.x, acc);
            acc = fmaf(ev.y, xv.y, acc);
            acc = fmaf(ev.z, xv.z, acc);
            acc = fmaf(ev.w, xv.w, acc);
        }
        #pragma unroll
        for (int off = 16; off; off >>= 1) acc += __shfl_xor_sync(0xffffffffu, acc, off);
        if (l == 0) {
            float d = __fsub_rn(__fadd_rn(xn, g_enorm[code]), 2.0f * acc);
            // d > 0 (distances ~512): float bits are order-preserving
            unsigned long long key =
                ((unsigned long long)__float_as_uint(d) << 32) | (unsigned)code;
            wbest = min(wbest, key);
        }
    }
    if (l == 0) swkey[w] = wbest;
    __syncthreads();

    if (tid == 0) {
        unsigned long long best = min(swkey[0], swkey[1]);
        int bi = (int)(best & 0xffffffffu);
        sbesti = bi;
        out[Q_ELEMS + 2 + row] = (float)bi;
        atomicMax(&g_maxidx, bi);
    }
    __syncthreads();
    const int idx = sbesti;

    // fused gather + straight-through + rowsq (2 x float4 per thread)
    float ss = 0.f;
    #pragma unroll
    for (int p = 0; p < 2; p++) {
        const int j = tid + p * 64;
        float4 qv = reinterpret_cast<const float4*>(emb + (size_t)idx * DIM)[j];
        float4 xv = reinterpret_cast<const float4*>(sx)[j];
        float4 ov;
        float d0 = __fsub_rn(qv.x, xv.x); ov.x = __fadd_rn(xv.x, d0);
        float d1 = __fsub_rn(qv.y, xv.y); ov.y = __fadd_rn(xv.y, d1);
        float d2 = __fsub_rn(qv.z, xv.z); ov.z = __fadd_rn(xv.z, d2);
        float d3 = __fsub_rn(qv.w, xv.w); ov.w = __fadd_rn(xv.w, d3);
        reinterpret_cast<float4*>(out + (size_t)row * DIM)[j] = ov;
        ss += (d0 * d0 + d1 * d1) + (d2 * d2 + d3 * d3);
    }
    #pragma unroll
    for (int off = 16; off; off >>= 1) ss += __shfl_xor_sync(0xffffffffu, ss, off);
    if (l == 0) sred[w] = ss;
    __syncthreads();
    if (tid == 0)
        g_rowsq[row] = sred[0] + sred[1];
}

// stage 1: 64 blocks x 256 threads, each reduces a fixed 256-row slice (deterministic)
__global__ void scalars_partial_kernel() {
    __shared__ float red[8];
    const int tid = threadIdx.x, w = tid >> 5, l = tid & 31;
    float s = g_rowsq[blockIdx.x * 256 + tid];
    #pragma unroll
    for (int off = 16; off; off >>= 1) s += __shfl_xor_sync(0xffffffffu, s, off);
    if (l == 0) red[w] = s;
    __syncthreads();
    if (tid == 0) {
        float t = 0.f;
        #pragma unroll
        for (int ww = 0; ww < 8; ww++) t += red[ww];
        g_part[blockIdx.x] = t;
    }
}

// stage 2: one warp finishes, fixed order
__global__ void scalars_final_kernel(float* __restrict__ out) {
    const int l = threadIdx.x;
    float s = g_part[l] + g_part[l + 32];
    #pragma unroll
    for (int off = 16; off; off >>= 1) s += __shfl_xor_sync(0xffffffffu, s, off);
    if (l == 0) {
        float mean = s / (float)Q_ELEMS;
        out[Q_ELEMS] = 1.25f * mean;
        float L = (float)(g_maxidx + 1);
        float avg = 1.0f / L;
        out[Q_ELEMS + 1] = expf(-avg * logf(avg + 1e-10f));
    }
}

extern "C" void kernel_launch(void* const* d_in, const int* in_sizes, int n_in,
                              void* d_out, int out_size) {
    const float* x   = (const float*)d_in[0];
    const float* emb = (const float*)d_in[1];
    float* out = (float*)d_out;

    cudaFuncSetAttribute(vq_gemm_kernel, cudaFuncAttributeMaxDynamicSharedMemorySize, SM_TOTAL);

    convert_kernel<<<(N_ROWS + N_CODES) / 8, 256>>>(x, emb);
    vq_gemm_kernel<<<dim3(N_ROWS / BM, N_CODES / BN), 256, SM_TOTAL>>>();
    select_kernel<<<N_ROWS, 64>>>(x, emb, out);
    scalars_partial_kernel<<<NPART, 256>>>();
    scalars_final_kernel<<<1, 32>>>(out);
}